// round 10
// baseline (speedup 1.0000x reference)
#include <cuda_runtime.h>
#include <math.h>

// ---- DCT basis as compile-time immediates (truncated-pi basis, <4e-7 err) --
#define P0 0.35355339059327373f
#define P1 0.4903926402016152f
#define P2 0.46193976625564337f
#define P3 0.4157348061512726f
#define P4 0.3535533905932738f
#define P5 0.2777851165098011f
#define P6 0.1913417161825449f
#define P7 0.09754516100806412f

#define DOT8(v,c0,c1,c2,c3,c4,c5,c6,c7) \
    fmaf((v)[7],(c7),fmaf((v)[6],(c6),fmaf((v)[5],(c5),fmaf((v)[4],(c4), \
    fmaf((v)[3],(c3),fmaf((v)[2],(c2),fmaf((v)[1],(c1),(v)[0]*(c0))))))))

// dst[i] = row_i(C) . src
#define MUL_ROWS(dst, src) do { \
    (dst)[0] = DOT8(src, P0, P0, P0, P0, P0, P0, P0, P0); \
    (dst)[1] = DOT8(src, P1, P3, P5, P7,-P7,-P5,-P3,-P1); \
    (dst)[2] = DOT8(src, P2, P6,-P6,-P2,-P2,-P6, P6, P2); \
    (dst)[3] = DOT8(src, P3,-P7,-P1,-P5, P5, P1, P7,-P3); \
    (dst)[4] = DOT8(src, P4,-P4,-P4, P4, P4,-P4,-P4, P4); \
    (dst)[5] = DOT8(src, P5,-P1, P7, P3,-P3,-P7, P1,-P5); \
    (dst)[6] = DOT8(src, P6,-P2, P2,-P6,-P6, P2,-P2, P6); \
    (dst)[7] = DOT8(src, P7,-P5, P3,-P1, P1,-P3, P5,-P7); \
} while (0)

// dst[i] = col_i(C) . src
#define MUL_COLS(dst, src) do { \
    (dst)[0] = DOT8(src, P0, P1, P2, P3, P4, P5, P6, P7); \
    (dst)[1] = DOT8(src, P0, P3, P6,-P7,-P4,-P1,-P2,-P5); \
    (dst)[2] = DOT8(src, P0, P5,-P6,-P1,-P4, P7, P2, P3); \
    (dst)[3] = DOT8(src, P0, P7,-P2,-P5, P4, P3,-P6,-P1); \
    (dst)[4] = DOT8(src, P0,-P7,-P2, P5, P4,-P3,-P6, P1); \
    (dst)[5] = DOT8(src, P0,-P5,-P6, P1,-P4,-P7, P2,-P3); \
    (dst)[6] = DOT8(src, P0,-P3, P6, P7,-P4, P1,-P2, P5); \
    (dst)[7] = DOT8(src, P0,-P1, P2,-P3, P4,-P5, P6,-P7); \
} while (0)

// Single fused kernel. Warp 0 of each CTA computes the tiny noise-MLP ->
// mask M (col-major, in shared) using only register shuffles, overlapped
// with the other warps' load/S1/T1 work. One __syncthreads gates first use.
// 2 lanes per 8x8 block; transposes via per-warp smem quadrant exchange.
// low = C^T((C X C^T).*M)C ; high = X - low. x read exactly once.
__global__ __launch_bounds__(256, 3) void dct_main(const float* __restrict__ x,
                                                   float* __restrict__ lo,
                                                   float* __restrict__ hi,
                                                   const float* __restrict__ noise,
                                                   const float* __restrict__ qmat,
                                                   const float* __restrict__ qmw,
                                                   const float* __restrict__ w1,
                                                   const float* __restrict__ b1,
                                                   const float* __restrict__ w2,
                                                   const float* __restrict__ b2,
                                                   const float* __restrict__ w3,
                                                   const float* __restrict__ b3)
{
    __shared__ __align__(16) float Ms[64];         // col-major mask
    __shared__ float4 xb[8][4][32];                // 16 KB exchange buffer

    int tid  = threadIdx.x;
    int wid  = tid >> 5;
    int lane = tid & 31;

    int p   = tid & 1;                     // half-block owner
    int g   = blockIdx.x * 128 + (tid >> 1);   // global 8x8-block id
    int img = g >> 6;
    int blk = g & 63;
    int base = (img << 12) + ((blk >> 3) << 9) + ((blk & 7) << 3);
    int r0   = p << 2;                     // first owned row

    const float* xp = x + base + (r0 << 6);
    float X[32];
    #pragma unroll
    for (int i = 0; i < 4; i++) {
        float4 a = *reinterpret_cast<const float4*>(xp + (i << 6));
        float4 b = *reinterpret_cast<const float4*>(xp + (i << 6) + 4);
        X[i*8+0]=a.x; X[i*8+1]=a.y; X[i*8+2]=a.z; X[i*8+3]=a.w;
        X[i*8+4]=b.x; X[i*8+5]=b.y; X[i*8+6]=b.z; X[i*8+7]=b.w;
    }

    // S1: A rows = (X * C^T) rows r0+i
    float A[32];
    #pragma unroll
    for (int i = 0; i < 4; i++) MUL_ROWS(&A[i*8], &X[i*8]);

    // T1: quadrant exchange with peer lane (lane^1) via smem
    #pragma unroll
    for (int i = 0; i < 4; i++) {
        float4 s = p ? make_float4(A[i*8+0], A[i*8+1], A[i*8+2], A[i*8+3])
                     : make_float4(A[i*8+4], A[i*8+5], A[i*8+6], A[i*8+7]);
        xb[wid][i][lane] = s;
    }
    __syncwarp();
    #pragma unroll
    for (int i = 0; i < 4; i++) {
        float4 r = xb[wid][i][lane ^ 1];
        if (p) { A[i*8+0]=r.x; A[i*8+1]=r.y; A[i*8+2]=r.z; A[i*8+3]=r.w; }
        else   { A[i*8+4]=r.x; A[i*8+5]=r.y; A[i*8+6]=r.z; A[i*8+7]=r.w; }
    }
    __syncwarp();                          // buffer reuse below

    // ---- warp 0: noise MLP -> mask (registers + shfl only) ----
    if (wid == 0) {
        const unsigned FULL = 0xffffffffu;
        const float inv_sqrt2 = 0.7071067811865476f;
        // layer 1 (lanes 0..15)
        float h1 = 0.f;
        if (lane < 16) {
            float z = fmaf(noise[0], w1[lane], b1[lane]);
            h1 = 0.5f * z * (1.0f + erff(z * inv_sqrt2));
        }
        // layer 2
        float h2 = 0.f;
        {
            float z = (lane < 16) ? b2[lane] : 0.f;
            #pragma unroll
            for (int k = 0; k < 16; k++) {
                float hk = __shfl_sync(FULL, h1, k);
                if (lane < 16) z = fmaf(hk, w2[k * 16 + lane], z);
            }
            if (lane < 16) h2 = 0.5f * z * (1.0f + erff(z * inv_sqrt2));
        }
        // layer 3 (lanes 0..17)
        float nr = 0.f;
        {
            float z = (lane < 18) ? b3[lane] : 0.f;
            #pragma unroll
            for (int k = 0; k < 16; k++) {
                float hk = __shfl_sync(FULL, h2, k);
                if (lane < 18) z = fmaf(hk, w3[k * 18 + lane], z);
            }
            nr = z;
        }
        float nr0 = __shfl_sync(FULL, nr, 0);
        float nr1 = __shfl_sync(FULL, nr, 1);
        // softmax(qmw) over lanes 0..15
        float q = (lane < 16) ? qmw[lane] : -1e30f;
        float m = q;
        #pragma unroll
        for (int d = 8; d >= 1; d >>= 1) m = fmaxf(m, __shfl_xor_sync(FULL, m, d));
        float e = (lane < 16) ? expf(q - m) : 0.f;
        float s = e;
        #pragma unroll
        for (int d = 8; d >= 1; d >>= 1) s += __shfl_xor_sync(FULL, s, d);
        float nr2i = __shfl_sync(FULL, nr, (lane < 16) ? (lane + 2) : 0);
        float coef = (lane < 16) ? (e / s * nr0 + nr1) * nr2i : 0.f;
        // mask, col-major: Ms[t] = sum_q coef[q]*qmat[q*64 + i*8 + c], t=c*8+i
        int t0 = lane, t1 = lane + 32;
        int i0 = t0 & 7, c0 = t0 >> 3;
        int i1 = t1 & 7, c1 = t1 >> 3;
        float s0 = 0.f, s1 = 0.f;
        #pragma unroll
        for (int k = 0; k < 16; k++) {
            float ck = __shfl_sync(FULL, coef, k);
            s0 = fmaf(ck, qmat[k * 64 + i0 * 8 + c0], s0);
            s1 = fmaf(ck, qmat[k * 64 + i1 * 8 + c1], s1);
        }
        Ms[t0] = s0;
        Ms[t1] = s1;
    }
    __syncthreads();                       // Ms ready for all warps

    // S2+mask+S3 per owned column c = r0+j (in place in A)
    #pragma unroll
    for (int j = 0; j < 4; j++) {
        float v[8], w[8], z[8];
        #pragma unroll
        for (int i = 0; i < 4; i++) { v[i] = A[i*8+j]; v[4+i] = A[i*8+4+j]; }
        MUL_ROWS(w, v);                    // spectrum column
        const float4 m0 = *reinterpret_cast<const float4*>(&Ms[(r0+j) << 3]);
        const float4 m1 = *reinterpret_cast<const float4*>(&Ms[((r0+j) << 3) + 4]);
        w[0]*=m0.x; w[1]*=m0.y; w[2]*=m0.z; w[3]*=m0.w;
        w[4]*=m1.x; w[5]*=m1.y; w[6]*=m1.z; w[7]*=m1.w;
        MUL_COLS(z, w);                    // Z column
        #pragma unroll
        for (int i = 0; i < 4; i++) { A[i*8+j] = z[i]; A[i*8+4+j] = z[4+i]; }
    }

    // T2: identical quadrant exchange (same buffer)
    #pragma unroll
    for (int i = 0; i < 4; i++) {
        float4 s = p ? make_float4(A[i*8+0], A[i*8+1], A[i*8+2], A[i*8+3])
                     : make_float4(A[i*8+4], A[i*8+5], A[i*8+6], A[i*8+7]);
        xb[wid][i][lane] = s;
    }
    __syncwarp();
    #pragma unroll
    for (int i = 0; i < 4; i++) {
        float4 r = xb[wid][i][lane ^ 1];
        if (p) { A[i*8+0]=r.x; A[i*8+1]=r.y; A[i*8+2]=r.z; A[i*8+3]=r.w; }
        else   { A[i*8+4]=r.x; A[i*8+5]=r.y; A[i*8+6]=r.z; A[i*8+7]=r.w; }
    }

    // S4: low rows = Z*C ; high = X - low
    float* lp = lo + base + (r0 << 6);
    float* hp = hi + base + (r0 << 6);
    #pragma unroll
    for (int i = 0; i < 4; i++) {
        float l[8];
        MUL_COLS(l, &A[i*8]);
        *reinterpret_cast<float4*>(lp + (i << 6))     = make_float4(l[0], l[1], l[2], l[3]);
        *reinterpret_cast<float4*>(lp + (i << 6) + 4) = make_float4(l[4], l[5], l[6], l[7]);
        *reinterpret_cast<float4*>(hp + (i << 6)) =
            make_float4(X[i*8+0]-l[0], X[i*8+1]-l[1], X[i*8+2]-l[2], X[i*8+3]-l[3]);
        *reinterpret_cast<float4*>(hp + (i << 6) + 4) =
            make_float4(X[i*8+4]-l[4], X[i*8+5]-l[5], X[i*8+6]-l[6], X[i*8+7]-l[7]);
    }
}

extern "C" void kernel_launch(void* const* d_in, const int* in_sizes, int n_in,
                              void* d_out, int out_size)
{
    const float* x     = (const float*)d_in[0];
    const float* noise = (const float*)d_in[1];
    const float* qmat  = (const float*)d_in[2];
    const float* qmw   = (const float*)d_in[3];
    const float* w1    = (const float*)d_in[4];
    const float* b1    = (const float*)d_in[5];
    const float* w2    = (const float*)d_in[6];
    const float* b2    = (const float*)d_in[7];
    const float* w3    = (const float*)d_in[8];
    const float* b3    = (const float*)d_in[9];

    float* out = (float*)d_out;
    int N = out_size / 2;                 // elements per output tensor
    float* lo = out;
    float* hi = out + N;

    int nblocks8x8 = N / 64;              // 2 lanes per block -> 128 blocks/CTA
    dct_main<<<nblocks8x8 / 128, 256>>>(x, lo, hi, noise, qmat, qmw,
                                        w1, b1, w2, b2, w3, b3);
}

// round 12
// speedup vs baseline: 2.1312x; 2.1312x over previous
#include <cuda_runtime.h>
#include <math.h>

// ---- DCT basis as compile-time immediates (truncated-pi basis, <4e-7 err) --
#define P0 0.35355339059327373f
#define P1 0.4903926402016152f
#define P2 0.46193976625564337f
#define P3 0.4157348061512726f
#define P4 0.3535533905932738f
#define P5 0.2777851165098011f
#define P6 0.1913417161825449f
#define P7 0.09754516100806412f

#define DOT8(v,c0,c1,c2,c3,c4,c5,c6,c7) \
    fmaf((v)[7],(c7),fmaf((v)[6],(c6),fmaf((v)[5],(c5),fmaf((v)[4],(c4), \
    fmaf((v)[3],(c3),fmaf((v)[2],(c2),fmaf((v)[1],(c1),(v)[0]*(c0))))))))

// dst[i] = row_i(C) . src
#define MUL_ROWS(dst, src) do { \
    (dst)[0] = DOT8(src, P0, P0, P0, P0, P0, P0, P0, P0); \
    (dst)[1] = DOT8(src, P1, P3, P5, P7,-P7,-P5,-P3,-P1); \
    (dst)[2] = DOT8(src, P2, P6,-P6,-P2,-P2,-P6, P6, P2); \
    (dst)[3] = DOT8(src, P3,-P7,-P1,-P5, P5, P1, P7,-P3); \
    (dst)[4] = DOT8(src, P4,-P4,-P4, P4, P4,-P4,-P4, P4); \
    (dst)[5] = DOT8(src, P5,-P1, P7, P3,-P3,-P7, P1,-P5); \
    (dst)[6] = DOT8(src, P6,-P2, P2,-P6,-P6, P2,-P2, P6); \
    (dst)[7] = DOT8(src, P7,-P5, P3,-P1, P1,-P3, P5,-P7); \
} while (0)

// dst[i] = col_i(C) . src
#define MUL_COLS(dst, src) do { \
    (dst)[0] = DOT8(src, P0, P1, P2, P3, P4, P5, P6, P7); \
    (dst)[1] = DOT8(src, P0, P3, P6,-P7,-P4,-P1,-P2,-P5); \
    (dst)[2] = DOT8(src, P0, P5,-P6,-P1,-P4, P7, P2, P3); \
    (dst)[3] = DOT8(src, P0, P7,-P2,-P5, P4, P3,-P6,-P1); \
    (dst)[4] = DOT8(src, P0,-P7,-P2, P5, P4,-P3,-P6, P1); \
    (dst)[5] = DOT8(src, P0,-P5,-P6, P1,-P4,-P7, P2,-P3); \
    (dst)[6] = DOT8(src, P0,-P3, P6, P7,-P4, P1,-P2, P5); \
    (dst)[7] = DOT8(src, P0,-P1, P2,-P3, P4,-P5, P6,-P7); \
} while (0)

// learned mask, COLUMN-major: g_Mc[c*8 + i] = M[i][c]
static __device__ float g_Mc[64];

__global__ void prep_kernel(const float* __restrict__ noise,
                            const float* __restrict__ qmat,
                            const float* __restrict__ qmw,
                            const float* __restrict__ w1, const float* __restrict__ b1,
                            const float* __restrict__ w2, const float* __restrict__ b2,
                            const float* __restrict__ w3, const float* __restrict__ b3)
{
    __shared__ float h1[16], h2[16], nr[18], coef[16];
    int t = threadIdx.x;  // 64 threads

    const float inv_sqrt2 = 0.7071067811865476f;
    if (t < 16) {
        float z = fmaf(noise[0], w1[t], b1[t]);
        h1[t] = 0.5f * z * (1.0f + erff(z * inv_sqrt2));
    }
    __syncthreads();
    if (t < 16) {
        float z = b2[t];
        #pragma unroll
        for (int k = 0; k < 16; k++) z = fmaf(h1[k], w2[k * 16 + t], z);
        h2[t] = 0.5f * z * (1.0f + erff(z * inv_sqrt2));
    }
    __syncthreads();
    if (t < 18) {
        float z = b3[t];
        #pragma unroll
        for (int k = 0; k < 16; k++) z = fmaf(h2[k], w3[k * 18 + t], z);
        nr[t] = z;
    }
    __syncthreads();
    if (t == 0) {
        float mx = qmw[0];
        #pragma unroll
        for (int i = 1; i < 16; i++) mx = fmaxf(mx, qmw[i]);
        float e[16], sum = 0.f;
        #pragma unroll
        for (int i = 0; i < 16; i++) { e[i] = expf(qmw[i] - mx); sum += e[i]; }
        float inv = 1.0f / sum;
        #pragma unroll
        for (int i = 0; i < 16; i++)
            coef[i] = (e[i] * inv * nr[0] + nr[1]) * nr[2 + i];
    }
    __syncthreads();

    if (t < 64) {
        int c = t >> 3, i = t & 7;          // write col-major
        float s = 0.f;
        #pragma unroll
        for (int q = 0; q < 16; q++) s = fmaf(coef[q], qmat[q * 64 + i * 8 + c], s);
        g_Mc[t] = s;
    }
}

// 2 lanes per 8x8 block. Lane parity p owns rows [4p,4p+4).
// Transposes via per-warp smem quadrant exchange (4 STS.128 + 4 LDS.128 each).
// low = C^T((C X C^T).*M)C ; high = X - low. x read exactly once.
__global__ __launch_bounds__(256, 3) void dct_main(const float* __restrict__ x,
                                                   float* __restrict__ lo,
                                                   float* __restrict__ hi)
{
    __shared__ __align__(16) float Ms[64];         // col-major mask
    __shared__ float4 xb[8][4][32];                // 16 KB exchange buffer

    int tid  = threadIdx.x;
    int wid  = tid >> 5;
    int lane = tid & 31;
    if (tid < 64) Ms[tid] = g_Mc[tid];
    __syncthreads();

    int p   = tid & 1;                     // half-block owner
    int g   = blockIdx.x * 128 + (tid >> 1);   // global 8x8-block id
    int img = g >> 6;
    int blk = g & 63;
    int base = (img << 12) + ((blk >> 3) << 9) + ((blk & 7) << 3);
    int r0   = p << 2;                     // first owned row

    const float* xp = x + base + (r0 << 6);
    float X[32];
    #pragma unroll
    for (int i = 0; i < 4; i++) {
        float4 a = *reinterpret_cast<const float4*>(xp + (i << 6));
        float4 b = *reinterpret_cast<const float4*>(xp + (i << 6) + 4);
        X[i*8+0]=a.x; X[i*8+1]=a.y; X[i*8+2]=a.z; X[i*8+3]=a.w;
        X[i*8+4]=b.x; X[i*8+5]=b.y; X[i*8+6]=b.z; X[i*8+7]=b.w;
    }

    // S1: A rows = (X * C^T) rows r0+i
    float A[32];
    #pragma unroll
    for (int i = 0; i < 4; i++) MUL_ROWS(&A[i*8], &X[i*8]);

    // T1: quadrant exchange with peer lane (lane^1) via smem
    #pragma unroll
    for (int i = 0; i < 4; i++) {
        float4 s = p ? make_float4(A[i*8+0], A[i*8+1], A[i*8+2], A[i*8+3])
                     : make_float4(A[i*8+4], A[i*8+5], A[i*8+6], A[i*8+7]);
        xb[wid][i][lane] = s;
    }
    __syncwarp();
    #pragma unroll
    for (int i = 0; i < 4; i++) {
        float4 r = xb[wid][i][lane ^ 1];
        if (p) { A[i*8+0]=r.x; A[i*8+1]=r.y; A[i*8+2]=r.z; A[i*8+3]=r.w; }
        else   { A[i*8+4]=r.x; A[i*8+5]=r.y; A[i*8+6]=r.z; A[i*8+7]=r.w; }
    }
    __syncwarp();                          // buffer reuse below

    // S2+mask+S3 per owned column c = r0+j (in place in A)
    #pragma unroll
    for (int j = 0; j < 4; j++) {
        float v[8], w[8], z[8];
        #pragma unroll
        for (int i = 0; i < 4; i++) { v[i] = A[i*8+j]; v[4+i] = A[i*8+4+j]; }
        MUL_ROWS(w, v);                    // spectrum column
        const float4 m0 = *reinterpret_cast<const float4*>(&Ms[(r0+j) << 3]);
        const float4 m1 = *reinterpret_cast<const float4*>(&Ms[((r0+j) << 3) + 4]);
        w[0]*=m0.x; w[1]*=m0.y; w[2]*=m0.z; w[3]*=m0.w;
        w[4]*=m1.x; w[5]*=m1.y; w[6]*=m1.z; w[7]*=m1.w;
        MUL_COLS(z, w);                    // Z column
        #pragma unroll
        for (int i = 0; i < 4; i++) { A[i*8+j] = z[i]; A[i*8+4+j] = z[4+i]; }
    }

    // T2: identical quadrant exchange (same buffer)
    #pragma unroll
    for (int i = 0; i < 4; i++) {
        float4 s = p ? make_float4(A[i*8+0], A[i*8+1], A[i*8+2], A[i*8+3])
                     : make_float4(A[i*8+4], A[i*8+5], A[i*8+6], A[i*8+7]);
        xb[wid][i][lane] = s;
    }
    __syncwarp();
    #pragma unroll
    for (int i = 0; i < 4; i++) {
        float4 r = xb[wid][i][lane ^ 1];
        if (p) { A[i*8+0]=r.x; A[i*8+1]=r.y; A[i*8+2]=r.z; A[i*8+3]=r.w; }
        else   { A[i*8+4]=r.x; A[i*8+5]=r.y; A[i*8+6]=r.z; A[i*8+7]=r.w; }
    }

    // S4: low rows = Z*C ; high = X - low
    float* lp = lo + base + (r0 << 6);
    float* hp = hi + base + (r0 << 6);
    #pragma unroll
    for (int i = 0; i < 4; i++) {
        float l[8];
        MUL_COLS(l, &A[i*8]);
        *reinterpret_cast<float4*>(lp + (i << 6))     = make_float4(l[0], l[1], l[2], l[3]);
        *reinterpret_cast<float4*>(lp + (i << 6) + 4) = make_float4(l[4], l[5], l[6], l[7]);
        *reinterpret_cast<float4*>(hp + (i << 6)) =
            make_float4(X[i*8+0]-l[0], X[i*8+1]-l[1], X[i*8+2]-l[2], X[i*8+3]-l[3]);
        *reinterpret_cast<float4*>(hp + (i << 6) + 4) =
            make_float4(X[i*8+4]-l[4], X[i*8+5]-l[5], X[i*8+6]-l[6], X[i*8+7]-l[7]);
    }
}

extern "C" void kernel_launch(void* const* d_in, const int* in_sizes, int n_in,
                              void* d_out, int out_size)
{
    const float* x     = (const float*)d_in[0];
    const float* noise = (const float*)d_in[1];
    const float* qmat  = (const float*)d_in[2];
    const float* qmw   = (const float*)d_in[3];
    const float* w1    = (const float*)d_in[4];
    const float* b1    = (const float*)d_in[5];
    const float* w2    = (const float*)d_in[6];
    const float* b2    = (const float*)d_in[7];
    const float* w3    = (const float*)d_in[8];
    const float* b3    = (const float*)d_in[9];

    float* out = (float*)d_out;
    int N = out_size / 2;                 // elements per output tensor
    float* lo = out;
    float* hi = out + N;

    prep_kernel<<<1, 64>>>(noise, qmat, qmw, w1, b1, w2, b2, w3, b3);

    int nblocks8x8 = N / 64;              // 2 lanes per block -> 128 blocks/CTA
    dct_main<<<nblocks8x8 / 128, 256>>>(x, lo, hi);
}